// round 2
// baseline (speedup 1.0000x reference)
#include <cuda_runtime.h>
#include <cstdint>

// Problem constants
#define Bv   8
#define Sv   1024
#define Dv   768
#define Hv   12
#define DHv  64
#define MLPv 3072
#define ROWS (Bv*Sv)            // 8192

// ---------------- scratch (static device memory; no allocs) ----------------
__device__ float g_xn [ROWS*Dv];
__device__ float g_q  [ROWS*Dv];
__device__ float g_k  [ROWS*Dv];
__device__ float g_v  [ROWS*Dv];
__device__ float g_ctx[ROWS*Dv];
__device__ float g_x2 [ROWS*Dv];
__device__ float g_xn2[ROWS*Dv];
__device__ float g_h1 [ROWS*MLPv];

// ---------------- LayerNorm: one block per row (768 cols) -------------------
__global__ __launch_bounds__(256)
void ln_kernel(const float* __restrict__ x, const float* __restrict__ g,
               const float* __restrict__ b, float* __restrict__ y) {
    int row = blockIdx.x;
    int t = threadIdx.x;
    const float* xr = x + (size_t)row * Dv;
    float v0 = xr[t], v1 = xr[t + 256], v2 = xr[t + 512];
    float s  = v0 + v1 + v2;
    float s2 = v0*v0 + v1*v1 + v2*v2;
    #pragma unroll
    for (int o = 16; o; o >>= 1) {
        s  += __shfl_xor_sync(0xFFFFFFFFu, s,  o);
        s2 += __shfl_xor_sync(0xFFFFFFFFu, s2, o);
    }
    __shared__ float rs[8], rs2[8];
    int w = t >> 5, lane = t & 31;
    if (lane == 0) { rs[w] = s; rs2[w] = s2; }
    __syncthreads();
    float tot = 0.f, tot2 = 0.f;
    #pragma unroll
    for (int i = 0; i < 8; i++) { tot += rs[i]; tot2 += rs2[i]; }
    float mu  = tot * (1.0f / Dv);
    float var = tot2 * (1.0f / Dv) - mu * mu;
    float inv = rsqrtf(var + 1e-6f);
    float* yr = y + (size_t)row * Dv;
    yr[t]       = (v0 - mu) * inv * g[t]       + b[t];
    yr[t + 256] = (v1 - mu) * inv * g[t + 256] + b[t + 256];
    yr[t + 512] = (v2 - mu) * inv * g[t + 512] + b[t + 512];
}

// ---------------- SGEMM 128x128x8, 8x8 per thread ---------------------------
// EPI: 0 = +bias ; 1 = +bias +res ; 2 = +bias, relu ; 3 = +bias, scatter to [B,H,S,64]
template<int EPI>
__global__ __launch_bounds__(256, 2)
void gemm_kernel(const float* __restrict__ A, const float* __restrict__ B,
                 const float* __restrict__ bias, const float* __restrict__ res,
                 float* __restrict__ C, int M, int N, int K) {
    __shared__ float As[8][128];
    __shared__ float Bs[8][128];
    const int tid = threadIdx.x;
    const int tx = tid & 15;
    const int ty = tid >> 4;
    const int rowBase = blockIdx.y * 128;
    const int colBase = blockIdx.x * 128;

    const int arow = tid >> 1;          // 0..127
    const int acol = (tid & 1) * 4;     // 0 or 4
    const int brow = tid >> 5;          // 0..7
    const int bcol = (tid & 31) * 4;    // 0..124

    const float* Ag = A + (size_t)(rowBase + arow) * K + acol;
    const float* Bg = B + (size_t)brow * N + colBase + bcol;

    float acc[8][8];
    #pragma unroll
    for (int i = 0; i < 8; i++)
        #pragma unroll
        for (int j = 0; j < 8; j++) acc[i][j] = 0.f;

    for (int kt = 0; kt < K; kt += 8) {
        float4 av = *(const float4*)(Ag + kt);
        float4 bv = *(const float4*)(Bg + (size_t)kt * N);
        As[acol + 0][arow] = av.x;
        As[acol + 1][arow] = av.y;
        As[acol + 2][arow] = av.z;
        As[acol + 3][arow] = av.w;
        *(float4*)&Bs[brow][bcol] = bv;
        __syncthreads();
        #pragma unroll
        for (int kk = 0; kk < 8; kk++) {
            float af[8], bf[8];
            *(float4*)&af[0] = *(const float4*)&As[kk][ty * 4];
            *(float4*)&af[4] = *(const float4*)&As[kk][64 + ty * 4];
            *(float4*)&bf[0] = *(const float4*)&Bs[kk][tx * 4];
            *(float4*)&bf[4] = *(const float4*)&Bs[kk][64 + tx * 4];
            #pragma unroll
            for (int i = 0; i < 8; i++)
                #pragma unroll
                for (int j = 0; j < 8; j++)
                    acc[i][j] = fmaf(af[i], bf[j], acc[i][j]);
        }
        __syncthreads();
    }

    #pragma unroll
    for (int i = 0; i < 8; i++) {
        int row = rowBase + ((i < 4) ? (ty * 4 + i) : (64 + ty * 4 + i - 4));
        #pragma unroll
        for (int j = 0; j < 8; j++) {
            int col = colBase + ((j < 4) ? (tx * 4 + j) : (64 + tx * 4 + j - 4));
            float v = acc[i][j] + bias[col];
            if (EPI == 1) v += res[(size_t)row * N + col];
            if (EPI == 2) v = fmaxf(v, 0.f);
            if (EPI == 3) {
                int bb = row >> 10, ss = row & 1023;
                int hh = col >> 6,  dd = col & 63;
                C[((size_t)(bb * Hv + hh) * Sv + ss) * DHv + dd] = v;
            } else {
                C[(size_t)row * N + col] = v;
            }
        }
    }
}

// ---------------- Attention (query rows < 512), flash-style fp32 ------------
// grid: (8 qtiles of 64 rows, H, B); block 256 (8 warps x 8 rows each)
__global__ __launch_bounds__(256)
void attn_kernel(const float* __restrict__ Q, const float* __restrict__ Kg,
                 const float* __restrict__ Vg, float* __restrict__ ctx) {
    __shared__ float Qs[64][64];
    __shared__ float Ks[32][65];
    __shared__ float Vs[32][65];
    const int b = blockIdx.z, h = blockIdx.y;
    const int bh = b * Hv + h;
    const int qbase = blockIdx.x * 64;
    const int tid = threadIdx.x;
    const int warp = tid >> 5, lane = tid & 31;

    const float* Qbh = Q + ((size_t)bh * Sv + qbase) * DHv;
    #pragma unroll
    for (int e = 0; e < 4; e++) {
        int lin = tid + e * 256;           // 0..1023 float4s
        int r = lin >> 4, c4 = (lin & 15) * 4;
        *(float4*)&Qs[r][c4] = *(const float4*)(Qbh + r * DHv + c4);
    }

    float m[8], l[8], acc0[8], acc1[8];
    #pragma unroll
    for (int r = 0; r < 8; r++) { m[r] = -1e30f; l[r] = 0.f; acc0[r] = 0.f; acc1[r] = 0.f; }

    const float* Kbh = Kg + (size_t)bh * Sv * DHv;
    const float* Vbh = Vg + (size_t)bh * Sv * DHv;

    for (int kt = 0; kt < Sv; kt += 32) {
        __syncthreads();
        #pragma unroll
        for (int e = 0; e < 8; e++) {
            int lin = tid + e * 256;       // 0..2047
            int r = lin >> 6, c = lin & 63;
            Ks[r][c] = Kbh[(kt + r) * DHv + c];
            Vs[r][c] = Vbh[(kt + r) * DHv + c];
        }
        __syncthreads();

        float s[8];
        #pragma unroll
        for (int r = 0; r < 8; r++) s[r] = 0.f;
        #pragma unroll
        for (int i = 0; i < 64; i++) {
            float kv = Ks[lane][i];
            #pragma unroll
            for (int r = 0; r < 8; r++)
                s[r] = fmaf(Qs[warp * 8 + r][i], kv, s[r]);
        }

        #pragma unroll
        for (int r = 0; r < 8; r++) {
            float sv = s[r] * 0.125f;      // 1/sqrt(64)
            float smax = sv;
            #pragma unroll
            for (int o = 16; o; o >>= 1)
                smax = fmaxf(smax, __shfl_xor_sync(0xFFFFFFFFu, smax, o));
            float mnew = fmaxf(m[r], smax);
            float p = __expf(sv - mnew);
            float corr = __expf(m[r] - mnew);
            float psum = p;
            #pragma unroll
            for (int o = 16; o; o >>= 1)
                psum += __shfl_xor_sync(0xFFFFFFFFu, psum, o);
            l[r] = l[r] * corr + psum;
            acc0[r] *= corr; acc1[r] *= corr;
            #pragma unroll
            for (int k0 = 0; k0 < 32; k0++) {
                float pk = __shfl_sync(0xFFFFFFFFu, p, k0);
                acc0[r] = fmaf(pk, Vs[k0][lane],      acc0[r]);
                acc1[r] = fmaf(pk, Vs[k0][lane + 32], acc1[r]);
            }
            m[r] = mnew;
        }
    }

    #pragma unroll
    for (int r = 0; r < 8; r++) {
        int qr = qbase + warp * 8 + r;
        float invl = 1.0f / l[r];
        size_t base = ((size_t)b * Sv + qr) * Dv + h * DHv;
        ctx[base + lane]      = acc0[r] * invl;
        ctx[base + lane + 32] = acc1[r] * invl;
    }
}

// ---------------- Masked rows (>=512): ctx = mean_k v, broadcast ------------
__global__ __launch_bounds__(256)
void meanv_kernel(const float* __restrict__ Vg, float* __restrict__ ctx) {
    const int h = blockIdx.x, b = blockIdx.y;
    const int bh = b * Hv + h;
    const int tid = threadIdx.x;
    const int d = tid & 63, slice = tid >> 6;   // 4 slices of 256 keys
    const float* Vbh = Vg + (size_t)bh * Sv * DHv;
    float s = 0.f;
    for (int k = slice * 256; k < slice * 256 + 256; k++)
        s += Vbh[k * DHv + d];
    __shared__ float red[4][64];
    __shared__ float mv[64];
    red[slice][d] = s;
    __syncthreads();
    if (tid < 64)
        mv[tid] = (red[0][tid] + red[1][tid] + red[2][tid] + red[3][tid]) * (1.0f / Sv);
    __syncthreads();
    float val = mv[d];
    for (int r = slice; r < 512; r += 4)
        ctx[((size_t)b * Sv + 512 + r) * Dv + h * DHv + d] = val;
}

// ---------------- driver -----------------------------------------------------
extern "C" void kernel_launch(void* const* d_in, const int* in_sizes, int n_in,
                              void* d_out, int out_size) {
    const float* x    = (const float*)d_in[0];
    const float* Wq   = (const float*)d_in[1];
    const float* bq   = (const float*)d_in[2];
    const float* Wk   = (const float*)d_in[3];
    const float* bk   = (const float*)d_in[4];
    const float* Wv   = (const float*)d_in[5];
    const float* bv   = (const float*)d_in[6];
    const float* Wo   = (const float*)d_in[7];
    const float* bo   = (const float*)d_in[8];
    const float* ln1g = (const float*)d_in[9];
    const float* ln1b = (const float*)d_in[10];
    const float* ln2g = (const float*)d_in[11];
    const float* ln2b = (const float*)d_in[12];
    const float* W1   = (const float*)d_in[13];
    const float* b1   = (const float*)d_in[14];
    const float* W2   = (const float*)d_in[15];
    const float* b2   = (const float*)d_in[16];
    float* out = (float*)d_out;

    float *xn, *q, *k, *v, *ctx, *x2, *xn2, *h1;
    cudaGetSymbolAddress((void**)&xn,  g_xn);
    cudaGetSymbolAddress((void**)&q,   g_q);
    cudaGetSymbolAddress((void**)&k,   g_k);
    cudaGetSymbolAddress((void**)&v,   g_v);
    cudaGetSymbolAddress((void**)&ctx, g_ctx);
    cudaGetSymbolAddress((void**)&x2,  g_x2);
    cudaGetSymbolAddress((void**)&xn2, g_xn2);
    cudaGetSymbolAddress((void**)&h1,  g_h1);

    // 1. LN1
    ln_kernel<<<ROWS, 256>>>(x, ln1g, ln1b, xn);

    // 2. QKV projections (scatter into [B,H,S,64])
    dim3 gD(Dv / 128, ROWS / 128);            // (6, 64)
    gemm_kernel<3><<<gD, 256>>>(xn, Wq, bq, nullptr, q, ROWS, Dv, Dv);
    gemm_kernel<3><<<gD, 256>>>(xn, Wk, bk, nullptr, k, ROWS, Dv, Dv);
    gemm_kernel<3><<<gD, 256>>>(xn, Wv, bv, nullptr, v, ROWS, Dv, Dv);

    // 3. Attention: real softmax for rows < 512; mean(v) for rows >= 512
    attn_kernel<<<dim3(8, Hv, Bv), 256>>>(q, k, v, ctx);
    meanv_kernel<<<dim3(Hv, Bv), 256>>>(v, ctx);

    // 4. Output projection + residual
    gemm_kernel<1><<<gD, 256>>>(ctx, Wo, bo, x, x2, ROWS, Dv, Dv);

    // 5. LN2
    ln_kernel<<<ROWS, 256>>>(x2, ln2g, ln2b, xn2);

    // 6. MLP
    dim3 gM(MLPv / 128, ROWS / 128);          // (24, 64)
    gemm_kernel<2><<<gM, 256>>>(xn2, W1, b1, nullptr, h1, ROWS, MLPv, Dv);
    gemm_kernel<1><<<gD, 256>>>(h1, W2, b2, x2, out, ROWS, Dv, MLPv);
}

// round 5
// speedup vs baseline: 2.3571x; 2.3571x over previous
#include <cuda_runtime.h>
#include <cstdint>

// Problem constants
#define Bv   8
#define Sv   1024
#define Dv   768
#define Hv   12
#define DHv  64
#define MLPv 3072
#define ROWS (Bv*Sv)            // 8192

// GEMM tiling
#define BK       32
#define LDK      36                     // 32 + 4 pad (conflict-free fragment LDS)
#define STAGE_FLTS (128*LDK)            // floats per operand per stage
#define SMEM_FLTS  (6*STAGE_FLTS)       // 3 stages x (A,B) = 110592 B
#define SMEMSZ     (SMEM_FLTS*4)

// ---------------- scratch (static device memory; no allocs) ----------------
__device__ float g_xn [ROWS*Dv];
__device__ float g_q  [ROWS*Dv];
__device__ float g_k  [ROWS*Dv];
__device__ float g_v  [ROWS*Dv];
__device__ float g_ctx[ROWS*Dv];
__device__ float g_x2 [ROWS*Dv];
__device__ float g_xn2[ROWS*Dv];
__device__ float g_h1 [ROWS*MLPv];
__device__ float g_wqT[Dv*Dv];
__device__ float g_wkT[Dv*Dv];
__device__ float g_wvT[Dv*Dv];
__device__ float g_woT[Dv*Dv];
__device__ float g_w1T[MLPv*Dv];   // [3072, 768]
__device__ float g_w2T[Dv*MLPv];   // [768, 3072]

// ---------------- helpers ----------------------------------------------------
__device__ __forceinline__ uint32_t smem_u32(const void* p) {
    uint32_t a;
    asm("{ .reg .u64 t; cvta.to.shared.u64 t, %1; cvt.u32.u64 %0, t; }" : "=r"(a) : "l"(p));
    return a;
}
__device__ __forceinline__ float rtf32(float x) {   // round-to-nearest tf32
    uint32_t u; asm("cvt.rna.tf32.f32 %0, %1;" : "=r"(u) : "f"(x));
    return __uint_as_float(u);
}

// ---------------- weight transpose + round to tf32 ---------------------------
// W [Kd, Nd] row-major  ->  WT [Nd, Kd]
__global__ __launch_bounds__(256)
void transpose_round(const float* __restrict__ W, float* __restrict__ WT, int Kd, int Nd) {
    __shared__ float t[32][33];
    int n0 = blockIdx.x * 32, k0 = blockIdx.y * 32;
    int tx = threadIdx.x & 31, ty = threadIdx.x >> 5;  // 32 x 8
    #pragma unroll
    for (int i = 0; i < 32; i += 8)
        t[ty + i][tx] = W[(size_t)(k0 + ty + i) * Nd + n0 + tx];
    __syncthreads();
    #pragma unroll
    for (int i = 0; i < 32; i += 8)
        WT[(size_t)(n0 + ty + i) * Kd + k0 + tx] = rtf32(t[tx][ty + i]);
}

// ---------------- LayerNorm (outputs rounded to tf32: GEMM-A operands) -------
__global__ __launch_bounds__(256)
void ln_kernel(const float* __restrict__ x, const float* __restrict__ g,
               const float* __restrict__ b, float* __restrict__ y) {
    int row = blockIdx.x;
    int t = threadIdx.x;
    const float* xr = x + (size_t)row * Dv;
    float v0 = xr[t], v1 = xr[t + 256], v2 = xr[t + 512];
    float s  = v0 + v1 + v2;
    float s2 = v0*v0 + v1*v1 + v2*v2;
    #pragma unroll
    for (int o = 16; o; o >>= 1) {
        s  += __shfl_xor_sync(0xFFFFFFFFu, s,  o);
        s2 += __shfl_xor_sync(0xFFFFFFFFu, s2, o);
    }
    __shared__ float rs[8], rs2[8];
    int w = t >> 5, lane = t & 31;
    if (lane == 0) { rs[w] = s; rs2[w] = s2; }
    __syncthreads();
    float tot = 0.f, tot2 = 0.f;
    #pragma unroll
    for (int i = 0; i < 8; i++) { tot += rs[i]; tot2 += rs2[i]; }
    float mu  = tot * (1.0f / Dv);
    float var = tot2 * (1.0f / Dv) - mu * mu;
    float inv = rsqrtf(var + 1e-6f);
    float* yr = y + (size_t)row * Dv;
    yr[t]       = rtf32((v0 - mu) * inv * g[t]       + b[t]);
    yr[t + 256] = rtf32((v1 - mu) * inv * g[t + 256] + b[t + 256]);
    yr[t + 512] = rtf32((v2 - mu) * inv * g[t + 512] + b[t + 512]);
}

// ---------------- tf32 tensor-core GEMM: C[M,N] = A[M,K] @ B[N,K]^T ----------
// mma.sync.aligned.m16n8k8 (legacy warp-MMA; valid on plain compute_103)
// EPI: 1 = +bias +res ; 2 = +bias, relu, round-tf32 ; 3 = +bias, scatter [B,H,S,64]
// mremap != 0: grid.y covers only query rows < 512 of each batch (Q projection)
template<int EPI>
__global__ __launch_bounds__(256)
void tgemm(const float* __restrict__ A, const float* __restrict__ Bw,
           const float* __restrict__ bias, const float* __restrict__ res,
           float* __restrict__ C, int M, int N, int K, int mremap) {
    extern __shared__ float smem[];
    float* sA = smem;                     // [3][128][LDK]
    float* sB = smem + 3 * STAGE_FLTS;
    const uint32_t saA = smem_u32(sA);
    const uint32_t saB = smem_u32(sB);

    const int tid = threadIdx.x;
    int by = blockIdx.y;
    if (mremap) by = (by >> 2) * 8 + (by & 3);
    const int rowBase = by * 128, colBase = blockIdx.x * 128;
    const int warp = tid >> 5, lane = tid & 31;
    const int wm = warp >> 2, wn = warp & 3;     // warps: 2 (m) x 4 (n)
    const int r = lane >> 2, c = lane & 3;

    auto load = [&](int j, int s) {
        int k0 = j * BK;
        #pragma unroll
        for (int e = 0; e < 4; e++) {
            int idx = tid + 256 * e;             // 0..1023
            int row = idx >> 3, kc = (idx & 7) * 4;
            const float* ga = A  + (size_t)(rowBase + row) * K + k0 + kc;
            const float* gb = Bw + (size_t)(colBase + row) * K + k0 + kc;
            uint32_t da = saA + (uint32_t)(s * STAGE_FLTS + row * LDK + kc) * 4;
            uint32_t db = saB + (uint32_t)(s * STAGE_FLTS + row * LDK + kc) * 4;
            asm volatile("cp.async.cg.shared.global [%0], [%1], 16;" :: "r"(da), "l"(ga));
            asm volatile("cp.async.cg.shared.global [%0], [%1], 16;" :: "r"(db), "l"(gb));
        }
        asm volatile("cp.async.commit_group;" ::: "memory");
    };

    float acc[4][4][4];
    #pragma unroll
    for (int mt = 0; mt < 4; mt++)
        #pragma unroll
        for (int nt = 0; nt < 4; nt++)
            #pragma unroll
            for (int i = 0; i < 4; i++) acc[mt][nt][i] = 0.f;

    load(0, 0);
    load(1, 1);

    const int nch = K / BK;
    for (int i = 0; i < nch; i++) {
        if (i + 2 < nch) load(i + 2, (i + 2) % 3);
        else asm volatile("cp.async.commit_group;" ::: "memory");
        asm volatile("cp.async.wait_group 2;" ::: "memory");
        __syncthreads();

        const uint32_t* pA = (const uint32_t*)(sA + (i % 3) * STAGE_FLTS);
        const uint32_t* pB = (const uint32_t*)(sB + (i % 3) * STAGE_FLTS);

        #pragma unroll
        for (int ks = 0; ks < 4; ks++) {
            uint32_t af[4][4], bf[4][2];
            #pragma unroll
            for (int mt = 0; mt < 4; mt++) {
                const uint32_t* p = pA + (wm * 64 + mt * 16 + r) * LDK + ks * 8 + c;
                af[mt][0] = p[0];
                af[mt][1] = p[8 * LDK];
                af[mt][2] = p[4];
                af[mt][3] = p[8 * LDK + 4];
            }
            #pragma unroll
            for (int nt = 0; nt < 4; nt++) {
                const uint32_t* p = pB + (wn * 32 + nt * 8 + r) * LDK + ks * 8 + c;
                bf[nt][0] = p[0];
                bf[nt][1] = p[4];
            }
            #pragma unroll
            for (int mt = 0; mt < 4; mt++)
                #pragma unroll
                for (int nt = 0; nt < 4; nt++)
                    asm volatile(
                        "mma.sync.aligned.m16n8k8.row.col.f32.tf32.tf32.f32 "
                        "{%0,%1,%2,%3}, {%4,%5,%6,%7}, {%8,%9}, {%0,%1,%2,%3};"
                        : "+f"(acc[mt][nt][0]), "+f"(acc[mt][nt][1]),
                          "+f"(acc[mt][nt][2]), "+f"(acc[mt][nt][3])
                        : "r"(af[mt][0]), "r"(af[mt][1]), "r"(af[mt][2]), "r"(af[mt][3]),
                          "r"(bf[nt][0]), "r"(bf[nt][1]));
        }
        __syncthreads();
    }

    // Epilogue: regs -> smem tile -> coalesced global stores
    float* tile = smem;                   // [128][132]
    #pragma unroll
    for (int mt = 0; mt < 4; mt++)
        #pragma unroll
        for (int nt = 0; nt < 4; nt++) {
            int r0 = wm * 64 + mt * 16 + r;
            int c0 = wn * 32 + nt * 8 + 2 * c;
            tile[r0 * 132 + c0]           = acc[mt][nt][0];
            tile[r0 * 132 + c0 + 1]       = acc[mt][nt][1];
            tile[(r0 + 8) * 132 + c0]     = acc[mt][nt][2];
            tile[(r0 + 8) * 132 + c0 + 1] = acc[mt][nt][3];
        }
    __syncthreads();

    float4 b4 = *(const float4*)(bias + colBase + lane * 4);
    int col0 = colBase + lane * 4;
    int hh = col0 >> 6, dd = col0 & 63;          // for EPI==3
    #pragma unroll
    for (int rr = 0; rr < 16; rr++) {
        int trow = warp * 16 + rr;
        int row  = rowBase + trow;
        float4 v = *(float4*)&tile[trow * 132 + lane * 4];
        v.x += b4.x; v.y += b4.y; v.z += b4.z; v.w += b4.w;
        if (EPI == 1) {
            float4 r4 = *(const float4*)(res + (size_t)row * N + col0);
            v.x += r4.x; v.y += r4.y; v.z += r4.z; v.w += r4.w;
        }
        if (EPI == 2) {
            v.x = rtf32(fmaxf(v.x, 0.f)); v.y = rtf32(fmaxf(v.y, 0.f));
            v.z = rtf32(fmaxf(v.z, 0.f)); v.w = rtf32(fmaxf(v.w, 0.f));
        }
        if (EPI == 3) {
            int bb = row >> 10, ss = row & 1023;
            *(float4*)&C[(((size_t)(bb * Hv + hh) * Sv + ss) * DHv) + dd] = v;
        } else {
            *(float4*)&C[(size_t)row * N + col0] = v;
        }
    }
}

// ---------------- Attention (query rows < 512), flash-style fp32 ------------
__global__ __launch_bounds__(256)
void attn_kernel(const float* __restrict__ Q, const float* __restrict__ Kg,
                 const float* __restrict__ Vg, float* __restrict__ ctx) {
    __shared__ float Qs[64][64];
    __shared__ float Ks[32][65];
    __shared__ float Vs[32][65];
    const int b = blockIdx.z, h = blockIdx.y;
    const int bh = b * Hv + h;
    const int qbase = blockIdx.x * 64;
    const int tid = threadIdx.x;
    const int warp = tid >> 5, lane = tid & 31;

    const float* Qbh = Q + ((size_t)bh * Sv + qbase) * DHv;
    #pragma unroll
    for (int e = 0; e < 4; e++) {
        int lin = tid + e * 256;
        int r = lin >> 4, c4 = (lin & 15) * 4;
        *(float4*)&Qs[r][c4] = *(const float4*)(Qbh + r * DHv + c4);
    }

    float m[8], l[8], acc0[8], acc1[8];
    #pragma unroll
    for (int r = 0; r < 8; r++) { m[r] = -1e30f; l[r] = 0.f; acc0[r] = 0.f; acc1[r] = 0.f; }

    const float* Kbh = Kg + (size_t)bh * Sv * DHv;
    const float* Vbh = Vg + (size_t)bh * Sv * DHv;

    for (int kt = 0; kt < Sv; kt += 32) {
        __syncthreads();
        #pragma unroll
        for (int e = 0; e < 8; e++) {
            int lin = tid + e * 256;
            int r = lin >> 6, c = lin & 63;
            Ks[r][c] = Kbh[(kt + r) * DHv + c];
            Vs[r][c] = Vbh[(kt + r) * DHv + c];
        }
        __syncthreads();

        float s[8];
        #pragma unroll
        for (int r = 0; r < 8; r++) s[r] = 0.f;
        #pragma unroll
        for (int i = 0; i < 64; i++) {
            float kv = Ks[lane][i];
            #pragma unroll
            for (int r = 0; r < 8; r++)
                s[r] = fmaf(Qs[warp * 8 + r][i], kv, s[r]);
        }

        #pragma unroll
        for (int r = 0; r < 8; r++) {
            float sv = s[r] * 0.125f;
            float smax = sv;
            #pragma unroll
            for (int o = 16; o; o >>= 1)
                smax = fmaxf(smax, __shfl_xor_sync(0xFFFFFFFFu, smax, o));
            float mnew = fmaxf(m[r], smax);
            float p = __expf(sv - mnew);
            float corr = __expf(m[r] - mnew);
            float psum = p;
            #pragma unroll
            for (int o = 16; o; o >>= 1)
                psum += __shfl_xor_sync(0xFFFFFFFFu, psum, o);
            l[r] = l[r] * corr + psum;
            acc0[r] *= corr; acc1[r] *= corr;
            #pragma unroll
            for (int k0 = 0; k0 < 32; k0++) {
                float pk = __shfl_sync(0xFFFFFFFFu, p, k0);
                acc0[r] = fmaf(pk, Vs[k0][lane],      acc0[r]);
                acc1[r] = fmaf(pk, Vs[k0][lane + 32], acc1[r]);
            }
            m[r] = mnew;
        }
    }

    #pragma unroll
    for (int r = 0; r < 8; r++) {
        int qr = qbase + warp * 8 + r;
        float invl = 1.0f / l[r];
        size_t base = ((size_t)b * Sv + qr) * Dv + h * DHv;
        ctx[base + lane]      = rtf32(acc0[r] * invl);
        ctx[base + lane + 32] = rtf32(acc1[r] * invl);
    }
}

// ---------------- Masked rows (>=512): ctx = mean_k v -----------------------
__global__ __launch_bounds__(256)
void meanv_kernel(const float* __restrict__ Vg, float* __restrict__ ctx) {
    const int h = blockIdx.x, b = blockIdx.y;
    const int bh = b * Hv + h;
    const int tid = threadIdx.x;
    const int d = tid & 63, slice = tid >> 6;
    const float* Vbh = Vg + (size_t)bh * Sv * DHv;
    float s = 0.f;
    for (int k = slice * 256; k < slice * 256 + 256; k++)
        s += Vbh[k * DHv + d];
    __shared__ float red[4][64];
    __shared__ float mv[64];
    red[slice][d] = s;
    __syncthreads();
    if (tid < 64)
        mv[tid] = rtf32((red[0][tid] + red[1][tid] + red[2][tid] + red[3][tid]) * (1.0f / Sv));
    __syncthreads();
    float val = mv[d];
    for (int r = slice; r < 512; r += 4)
        ctx[((size_t)b * Sv + 512 + r) * Dv + h * DHv + d] = val;
}

// ---------------- driver -----------------------------------------------------
extern "C" void kernel_launch(void* const* d_in, const int* in_sizes, int n_in,
                              void* d_out, int out_size) {
    const float* x    = (const float*)d_in[0];
    const float* Wq   = (const float*)d_in[1];
    const float* bq   = (const float*)d_in[2];
    const float* Wk   = (const float*)d_in[3];
    const float* bk   = (const float*)d_in[4];
    const float* Wv   = (const float*)d_in[5];
    const float* bv   = (const float*)d_in[6];
    const float* Wo   = (const float*)d_in[7];
    const float* bo   = (const float*)d_in[8];
    const float* ln1g = (const float*)d_in[9];
    const float* ln1b = (const float*)d_in[10];
    const float* ln2g = (const float*)d_in[11];
    const float* ln2b = (const float*)d_in[12];
    const float* W1   = (const float*)d_in[13];
    const float* b1   = (const float*)d_in[14];
    const float* W2   = (const float*)d_in[15];
    const float* b2   = (const float*)d_in[16];
    float* out = (float*)d_out;

    float *xn, *q, *k, *v, *ctx, *x2, *xn2, *h1;
    float *wqT, *wkT, *wvT, *woT, *w1T, *w2T;
    cudaGetSymbolAddress((void**)&xn,  g_xn);
    cudaGetSymbolAddress((void**)&q,   g_q);
    cudaGetSymbolAddress((void**)&k,   g_k);
    cudaGetSymbolAddress((void**)&v,   g_v);
    cudaGetSymbolAddress((void**)&ctx, g_ctx);
    cudaGetSymbolAddress((void**)&x2,  g_x2);
    cudaGetSymbolAddress((void**)&xn2, g_xn2);
    cudaGetSymbolAddress((void**)&h1,  g_h1);
    cudaGetSymbolAddress((void**)&wqT, g_wqT);
    cudaGetSymbolAddress((void**)&wkT, g_wkT);
    cudaGetSymbolAddress((void**)&wvT, g_wvT);
    cudaGetSymbolAddress((void**)&woT, g_woT);
    cudaGetSymbolAddress((void**)&w1T, g_w1T);
    cudaGetSymbolAddress((void**)&w2T, g_w2T);

    cudaFuncSetAttribute(tgemm<1>, cudaFuncAttributeMaxDynamicSharedMemorySize, SMEMSZ);
    cudaFuncSetAttribute(tgemm<2>, cudaFuncAttributeMaxDynamicSharedMemorySize, SMEMSZ);
    cudaFuncSetAttribute(tgemm<3>, cudaFuncAttributeMaxDynamicSharedMemorySize, SMEMSZ);

    // Weight transposes (rounded to tf32)
    transpose_round<<<dim3(Dv/32,   Dv/32),   256>>>(Wq, wqT, Dv,   Dv);
    transpose_round<<<dim3(Dv/32,   Dv/32),   256>>>(Wk, wkT, Dv,   Dv);
    transpose_round<<<dim3(Dv/32,   Dv/32),   256>>>(Wv, wvT, Dv,   Dv);
    transpose_round<<<dim3(Dv/32,   Dv/32),   256>>>(Wo, woT, Dv,   Dv);
    transpose_round<<<dim3(MLPv/32, Dv/32),   256>>>(W1, w1T, Dv,   MLPv);
    transpose_round<<<dim3(Dv/32,   MLPv/32), 256>>>(W2, w2T, MLPv, Dv);

    // 1. LN1
    ln_kernel<<<ROWS, 256>>>(x, ln1g, ln1b, xn);

    // 2. QKV projections (tensor core, scatter into [B,H,S,64]).
    //    Q only needed for query rows < 512 of each batch -> half M with tile remap.
    dim3 gD(Dv/128, ROWS/128);             // (6, 64)
    dim3 gQ(Dv/128, ROWS/256);             // (6, 32) remapped
    tgemm<3><<<gQ, 256, SMEMSZ>>>(xn, wqT, bq, nullptr, q, ROWS, Dv, Dv, 1);
    tgemm<3><<<gD, 256, SMEMSZ>>>(xn, wkT, bk, nullptr, k, ROWS, Dv, Dv, 0);
    tgemm<3><<<gD, 256, SMEMSZ>>>(xn, wvT, bv, nullptr, v, ROWS, Dv, Dv, 0);

    // 3. Attention
    attn_kernel<<<dim3(8, Hv, Bv), 256>>>(q, k, v, ctx);
    meanv_kernel<<<dim3(Hv, Bv), 256>>>(v, ctx);

    // 4. Output projection + residual
    tgemm<1><<<gD, 256, SMEMSZ>>>(ctx, woT, bo, x, x2, ROWS, Dv, Dv, 0);

    // 5. LN2
    ln_kernel<<<ROWS, 256>>>(x2, ln2g, ln2b, xn2);

    // 6. MLP
    dim3 gM(MLPv/128, ROWS/128);           // (24, 64)
    tgemm<2><<<gM, 256, SMEMSZ>>>(xn2, w1T, b1, nullptr, h1, ROWS, MLPv, Dv, 0);
    tgemm<1><<<gD, 256, SMEMSZ>>>(h1, w2T, b2, x2, out, ROWS, Dv, MLPv, 0);
}